// round 8
// baseline (speedup 1.0000x reference)
#include <cuda_runtime.h>
#include <math.h>

// Problem constants
#define BB        4
#define NPTS      4096
#define MPTS      4096
#define TPB       1024
#define SRCB      128               // sources per block
#define PARTS     8                 // warps (target parts) per source group
#define BLK_PER_B 32                // blocks per batch
#define NBLK      (BB * BLK_PER_B)  // 128 blocks total, 1 per SM
#define NPAIRS    (MPTS / 2)        // 2048 target pairs per batch
#define PPP       (NPAIRS / PARTS)  // 256 pairs per part
#define GRPS      8                 // groups per part
#define GP        (PPP / GRPS)      // 32 pairs per group
#define NQG       (PARTS * GRPS)    // 64 (part,group) cells per source
#define ICP_STEPS 16
#define ICP_TOL   1e-6

// ---------------------------------------------------------------------------
// Device-global state. Counters monotonic within a launch, reset by the final
// block -> replay-clean for CUDA graphs.
// ---------------------------------------------------------------------------
__device__ float    g_wsum[BB][128][16];   // [b][row = 32*r sources][q]
__device__ float    g_Rt[BB][12];
__device__ double   g_errlast[BB];
__device__ int      g_done;
__device__ unsigned g_gen;
__device__ unsigned g_momcntB[BB];         // per-batch arrivals
__device__ unsigned g_fincnt;              // batch-last arrivals

// ---------------------------------------------------------------------------
__device__ __forceinline__ void xform(const float* Mtx,
                                      float px, float py, float pz,
                                      float& qx, float& qy, float& qz) {
    qx = fmaf(Mtx[0], px, fmaf(Mtx[1], py, fmaf(Mtx[2], pz, Mtx[9])));
    qy = fmaf(Mtx[3], px, fmaf(Mtx[4], py, fmaf(Mtx[5], pz, Mtx[10])));
    qz = fmaf(Mtx[6], px, fmaf(Mtx[7], py, fmaf(Mtx[8], pz, Mtx[11])));
}

// packed f32x2 helpers (per-half rounding identical to scalar FFMA)
__device__ __forceinline__ unsigned long long pk2(float v) {
    unsigned long long r;
    asm("mov.b64 %0, {%1, %1};" : "=l"(r) : "f"(v));
    return r;
}
__device__ __forceinline__ unsigned long long fma2(unsigned long long a,
                                                   unsigned long long b,
                                                   unsigned long long c) {
    unsigned long long d;
    asm("fma.rn.f32x2 %0, %1, %2, %3;" : "=l"(d) : "l"(a), "l"(b), "l"(c));
    return d;
}
__device__ __forceinline__ void upk2(unsigned long long v, float& lo, float& hi) {
    asm("mov.b64 {%0, %1}, %2;" : "=f"(lo), "=f"(hi) : "l"(v));
}

// ---------------------------------------------------------------------------
// Kabsch from accumulated sums (identical arithmetic to R2-R7).
// ---------------------------------------------------------------------------
__device__ void kabsch_sums(const double* S, float* Rt) {
    const double invN = 1.0 / (double)NPTS;
    double cs[3] = { S[0] * invN, S[1] * invN, S[2] * invN };
    double ct[3] = { S[3] * invN, S[4] * invN, S[5] * invN };

    float H[3][3];
    for (int i = 0; i < 3; ++i)
        for (int j = 0; j < 3; ++j)
            H[i][j] = (float)(S[6 + 3 * i + j] - (double)NPTS * cs[i] * ct[j]);

    float A[3][3];
    for (int i = 0; i < 3; ++i)
        for (int j = 0; j < 3; ++j)
            A[i][j] = H[0][i] * H[0][j] + H[1][i] * H[1][j] + H[2][i] * H[2][j];

    float V[3][3] = { {1,0,0},{0,1,0},{0,0,1} };
    const float diagmag = fabsf(A[0][0]) + fabsf(A[1][1]) + fabsf(A[2][2]);
    const float offeps  = diagmag * 1e-9f;
    for (int sweep = 0; sweep < 8; ++sweep) {
        const float off = fabsf(A[0][1]) + fabsf(A[0][2]) + fabsf(A[1][2]);
        if (off <= offeps) break;
        for (int pq = 0; pq < 3; ++pq) {
            const int p = (pq == 2) ? 1 : 0;
            const int q = (pq == 0) ? 1 : 2;
            const float apq = A[p][q];
            if (fabsf(apq) <= 0.0f) continue;
            const float theta = (A[q][q] - A[p][p]) / (2.0f * apq);
            const float tt = ((theta >= 0.0f) ? 1.0f : -1.0f) /
                             (fabsf(theta) + sqrtf(theta * theta + 1.0f));
            const float c = rsqrtf(tt * tt + 1.0f);
            const float s = tt * c;
            for (int k = 0; k < 3; ++k) { float a1 = A[p][k], a2 = A[q][k];
                A[p][k] = c * a1 - s * a2; A[q][k] = s * a1 + c * a2; }
            for (int k = 0; k < 3; ++k) { float a1 = A[k][p], a2 = A[k][q];
                A[k][p] = c * a1 - s * a2; A[k][q] = s * a1 + c * a2; }
            for (int k = 0; k < 3; ++k) { float v1 = V[k][p], v2 = V[k][q];
                V[k][p] = c * v1 - s * v2; V[k][q] = s * v1 + c * v2; }
        }
    }

    int id[3] = { 0, 1, 2 };
    float w[3] = { A[0][0], A[1][1], A[2][2] };
    if (w[id[0]] < w[id[1]]) { int t0 = id[0]; id[0] = id[1]; id[1] = t0; }
    if (w[id[0]] < w[id[2]]) { int t0 = id[0]; id[0] = id[2]; id[2] = t0; }
    if (w[id[1]] < w[id[2]]) { int t0 = id[1]; id[1] = id[2]; id[2] = t0; }

    float v1[3], v2[3], v3[3];
    for (int k = 0; k < 3; ++k) { v1[k] = V[k][id[0]]; v2[k] = V[k][id[1]]; v3[k] = V[k][id[2]]; }

    float u1[3], u2[3], u3[3];
    for (int i = 0; i < 3; ++i) u1[i] = H[i][0] * v1[0] + H[i][1] * v1[1] + H[i][2] * v1[2];
    {
        float n1 = u1[0]*u1[0] + u1[1]*u1[1] + u1[2]*u1[2];
        float r = (n1 > 0.0f) ? rsqrtf(n1) : 0.0f;
        u1[0] *= r; u1[1] *= r; u1[2] *= r;
    }
    for (int i = 0; i < 3; ++i) u2[i] = H[i][0] * v2[0] + H[i][1] * v2[1] + H[i][2] * v2[2];
    {
        float pr = u1[0]*u2[0] + u1[1]*u2[1] + u1[2]*u2[2];
        u2[0] -= pr * u1[0]; u2[1] -= pr * u1[1]; u2[2] -= pr * u1[2];
        float n2 = u2[0]*u2[0] + u2[1]*u2[1] + u2[2]*u2[2];
        float r = (n2 > 0.0f) ? rsqrtf(n2) : 0.0f;
        u2[0] *= r; u2[1] *= r; u2[2] *= r;
    }
    u3[0] = u1[1]*u2[2] - u1[2]*u2[1];
    u3[1] = u1[2]*u2[0] - u1[0]*u2[2];
    u3[2] = u1[0]*u2[1] - u1[1]*u2[0];

    const float d =
        v1[0] * (v2[1]*v3[2] - v2[2]*v3[1]) -
        v1[1] * (v2[0]*v3[2] - v2[2]*v3[0]) +
        v1[2] * (v2[0]*v3[1] - v2[1]*v3[0]);

    float R[9];
    for (int i = 0; i < 3; ++i)
        for (int j = 0; j < 3; ++j)
            R[3 * i + j] = v1[i]*u1[j] + v2[i]*u2[j] + d * v3[i]*u3[j];
    for (int k = 0; k < 9; ++k) Rt[k] = R[k];
    for (int i = 0; i < 3; ++i)
        Rt[9 + i] = (float)ct[i] - (R[3*i]*(float)cs[0] + R[3*i+1]*(float)cs[1]
                                    + R[3*i+2]*(float)cs[2]);
}

// ---------------------------------------------------------------------------
// Warp shfl reduction identical to the original block_reduce16 intra-warp
// stage; lane0 writes its warp row to g_wsum. Caller: threads 0..127 only.
// ---------------------------------------------------------------------------
__device__ __forceinline__ void warp_reduce16_store(const float v[16],
                                                    int b, int row) {
    const int lane = threadIdx.x & 31;
#pragma unroll
    for (int q = 0; q < 16; ++q) {
        float r = v[q];
#pragma unroll
        for (int o = 16; o > 0; o >>= 1) r += __shfl_down_sync(0xffffffffu, r, o);
        if (lane == 0) g_wsum[b][row][q] = r;
    }
}

// ---------------------------------------------------------------------------
// Persistent fused ICP kernel: 128 blocks x 1024 threads (1 block/SM).
// Phase A: min-VALUE-only scan (FMNMX), per-(part,group) mins to smem.
// Phase B: exact index recovery by rescanning only the first min-group.
// ---------------------------------------------------------------------------
extern __shared__ __align__(16) float smem_dyn[];

__global__ void __launch_bounds__(TPB, 1)
icp_kernel(const float* __restrict__ src, const float* __restrict__ tgt,
           float* __restrict__ out) {
    // dynamic smem layout
    float* tgP   = smem_dyn;                       // 2048 pairs * 8 f = 64KB
    float* gmins = tgP + NPAIRS * 8;               // 64 * 128 f = 32KB
    float* srcP  = gmins + NQG * SRCB;             // 128*3
    float* mw    = srcP + SRCB * 3;                // 128*3
    float* RtSh  = mw + SRCB * 3;                  // 12

    __shared__ double sums[BB][16];
    __shared__ float  Rsh[BB][12];
    __shared__ int    convf[BB];
    __shared__ int    s_isfin;
    __shared__ int    s_done;

    const int tid  = threadIdx.x;
    const int w    = tid >> 5;                 // warp 0..31
    const int lane = tid & 31;
    const int g    = w >> 3;                   // source group 0..3
    const int q    = w & 7;                    // target part 0..7
    const int srcl = g * 32 + lane;            // this lane's source (scan phase)
    const int b    = blockIdx.x >> 5;          // batch
    const int blk2 = blockIdx.x & 31;          // 128-source slice

    // ---- stage full target set; pair p: [x0 x1 y0 y1 z0 z1 w0 w1]
    {
        const float* T = tgt + (size_t)b * MPTS * 3;
        for (int k = tid; k < MPTS; k += TPB) {
            float x = T[3 * k], y = T[3 * k + 1], z = T[3 * k + 2];
            float ww = fmaf(x, x, fmaf(y, y, z * z));
            int p = k >> 1, h = k & 1;
            tgP[p * 8 + 0 + h] = x;
            tgP[p * 8 + 2 + h] = y;
            tgP[p * 8 + 4 + h] = z;
            tgP[p * 8 + 6 + h] = ww;
        }
    }
    if (tid < SRCB * 3) {
        srcP[tid] = src[(size_t)(b * NPTS + blk2 * SRCB) * 3 + tid];
    }
    __syncthreads();

    const ulonglong2* tg2 = (const ulonglong2*)tgP;   // pair p = tg2[2p], tg2[2p+1]

    for (int k = 0; k < ICP_STEPS; ++k) {
        // ---- wait for generation k, stage transform
        if (k > 0) {
            if (tid == 0) {
                while (*(volatile unsigned*)&g_gen < (unsigned)k) __nanosleep(32);
                __threadfence();
            }
            __syncthreads();
            if (tid < 12) RtSh[tid] = g_Rt[b][tid];
            __syncthreads();
        }

        // ---- transform this lane's source point (identity at k==0)
        const float px = srcP[3 * srcl], py = srcP[3 * srcl + 1], pz = srcP[3 * srcl + 2];
        float wx, wy, wz;
        if (k == 0) {
            const float I[12] = {1.f,0.f,0.f, 0.f,1.f,0.f, 0.f,0.f,1.f, 0.f,0.f,0.f};
            xform(I, px, py, pz, wx, wy, wz);
        } else {
            xform(RtSh, px, py, pz, wx, wy, wz);
        }

        // ================= Phase A: min-value-only scan =====================
        {
            const unsigned long long ax2 = pk2(-2.f * wx);
            const unsigned long long ay2 = pk2(-2.f * wy);
            const unsigned long long az2 = pk2(-2.f * wz);
            const int pbase = q * PPP;

#pragma unroll
            for (int grp = 0; grp < GRPS; ++grp) {
                const int gp = pbase + grp * GP;
                float gmE = 3.4e38f, gmO = 3.4e38f;
#pragma unroll 8
                for (int i = 0; i < GP; ++i) {
                    const ulonglong2 A  = tg2[2 * (gp + i)];
                    const ulonglong2 Bv = tg2[2 * (gp + i) + 1];
                    unsigned long long s01 =
                        fma2(ax2, A.x, fma2(ay2, A.y, fma2(az2, Bv.x, Bv.y)));
                    float e, o;
                    upk2(s01, e, o);
                    gmE = fminf(gmE, e);
                    gmO = fminf(gmO, o);
                }
                gmins[(q * GRPS + grp) * SRCB + srcl] = fminf(gmE, gmO);
            }
        }
        if (q == 0) {   // one copy of the transformed point per source
            mw[3 * srcl] = wx; mw[3 * srcl + 1] = wy; mw[3 * srcl + 2] = wz;
        }
        __syncthreads();

        // ============ Phase B + moments (threads 0..127, src = tid) ========
        if (tid < SRCB) {
            // global min over 64 group mins (exact; value identical to full scan)
            float m = gmins[tid];
#pragma unroll 8
            for (int t = 1; t < NQG; ++t) m = fminf(m, gmins[t * SRCB + tid]);

            // first (ascending-j) group attaining m
            int qg = 0;
#pragma unroll 8
            for (int t = NQG - 1; t >= 0; --t)
                if (gmins[t * SRCB + tid] == m) qg = t;

            // rescan that group's 32 pairs, identical arithmetic, smallest j match
            const float mx = mw[3 * tid], my = mw[3 * tid + 1], mz = mw[3 * tid + 2];
            const unsigned long long ax2 = pk2(-2.f * mx);
            const unsigned long long ay2 = pk2(-2.f * my);
            const unsigned long long az2 = pk2(-2.f * mz);
            const int pstart = qg * GP;   // qg*32 pairs == part*256 + grp*32

            int jb = 0xFFFF;
#pragma unroll 4
            for (int i = 0; i < GP; ++i) {
                const ulonglong2 A  = tg2[2 * (pstart + i)];
                const ulonglong2 Bv = tg2[2 * (pstart + i) + 1];
                unsigned long long s01 =
                    fma2(ax2, A.x, fma2(ay2, A.y, fma2(az2, Bv.x, Bv.y)));
                float e, o;
                upk2(s01, e, o);
                if (e == m) jb = min(jb, 2 * (pstart + i));
                if (o == m) jb = min(jb, 2 * (pstart + i) + 1);
            }
            const unsigned j = (unsigned)jb;
            const float    s = m;

            const float a2v = fmaf(mx, mx, fmaf(my, my, mz * mz));
            const float d2  = fmaxf(s + a2v, 0.f);
            const float ec  = sqrtf(d2);

            const unsigned p = j >> 1, h = j & 1;
            const float tx = tgP[p * 8 + 0 + h];
            const float ty = tgP[p * 8 + 2 + h];
            const float tz = tgP[p * 8 + 4 + h];

            const float v[16] = { mx, my, mz, tx, ty, tz,
                                  mx * tx, mx * ty, mx * tz,
                                  my * tx, my * ty, my * tz,
                                  mz * tx, mz * ty, mz * tz, ec };
            warp_reduce16_store(v, b, blk2 * 4 + (tid >> 5));

            srcP[3 * tid] = mx; srcP[3 * tid + 1] = my; srcP[3 * tid + 2] = mz;
        }
        __threadfence();
        __syncthreads();

        // ---- two-level arrival: per-batch counter, then tiny global counter
        if (tid == 0) {
            s_isfin = 0;
            unsigned oldb = atomicAdd(&g_momcntB[b], 1u);
            if (oldb == (unsigned)(BLK_PER_B * (k + 1) - 1)) {
                unsigned oldf = atomicAdd(&g_fincnt, 1u);
                s_isfin = (oldf == (unsigned)(BB * (k + 1) - 1)) ? 1 : 0;
            }
        }
        __syncthreads();

        if (s_isfin) {
            if (tid == 0) __threadfence();
            __syncthreads();
            if (tid < BB * 16) {
                const int bb = tid >> 4, qq = tid & 15;
                double acc64 = 0.0;
                for (int bx = 0; bx < 16; ++bx) {
                    float acc32 = 0.f;
#pragma unroll
                    for (int ww = 0; ww < 8; ++ww)
                        acc32 += g_wsum[bb][bx * 8 + ww][qq];
                    acc64 += (double)acc32;
                }
                sums[bb][qq] = acc64;
            }
            __syncthreads();

            double errnew = 0.0;
            if (tid < BB) {
                errnew = sums[tid][15] / (double)NPTS;
                const double errlast = (k == 0) ? 0.0 : g_errlast[tid];
                convf[tid] = (fabs(errnew - errlast) < ICP_TOL) ? 1 : 0;
                kabsch_sums(sums[tid], Rsh[tid]);
            }
            __syncthreads();
            if (tid == 0) {
                const int all  = convf[0] & convf[1] & convf[2] & convf[3];
                const int prev = (k == 0) ? 0 : g_done;
                s_done = prev | all;
                g_done = s_done;
            }
            __syncthreads();
            if (tid < BB) {
                if (!s_done) {
                    g_errlast[tid] = errnew;
                    for (int qq = 0; qq < 12; ++qq) g_Rt[tid][qq] = Rsh[tid][qq];
                } else {
                    for (int qq = 0; qq < 12; ++qq)
                        g_Rt[tid][qq] = (qq == 0 || qq == 4 || qq == 8) ? 1.f : 0.f;
                }
            }
            __threadfence();
            __syncthreads();
            if (tid == 0) atomicExch(&g_gen, (unsigned)(k + 1));   // release
        }
    }

    // ======================= FINAL kabsch(source, temporal) ==================
    if (tid == 0) {
        while (*(volatile unsigned*)&g_gen < (unsigned)ICP_STEPS) __nanosleep(32);
        __threadfence();
    }
    __syncthreads();
    if (tid < 12) RtSh[tid] = g_Rt[b][tid];
    __syncthreads();

    if (tid < SRCB) {
        const float px = srcP[3 * tid], py = srcP[3 * tid + 1], pz = srcP[3 * tid + 2];
        float wx, wy, wz;
        xform(RtSh, px, py, pz, wx, wy, wz);

        const float sx = src[3 * (b * NPTS + blk2 * SRCB + tid)];
        const float sy = src[3 * (b * NPTS + blk2 * SRCB + tid) + 1];
        const float sz = src[3 * (b * NPTS + blk2 * SRCB + tid) + 2];

        const float v[16] = { sx, sy, sz, wx, wy, wz,
                              sx * wx, sx * wy, sx * wz,
                              sy * wx, sy * wy, sy * wz,
                              sz * wx, sz * wy, sz * wz, 0.f };
        warp_reduce16_store(v, b, blk2 * 4 + (tid >> 5));
    }
    __threadfence();
    __syncthreads();
    if (tid == 0) {
        s_isfin = 0;
        unsigned oldb = atomicAdd(&g_momcntB[b], 1u);
        if (oldb == (unsigned)(BLK_PER_B * (ICP_STEPS + 1) - 1)) {
            unsigned oldf = atomicAdd(&g_fincnt, 1u);
            s_isfin = (oldf == (unsigned)(BB * (ICP_STEPS + 1) - 1)) ? 1 : 0;
        }
    }
    __syncthreads();
    if (!s_isfin) return;

    // ---- last block: final kabsch, output, counter reset for next replay
    if (tid == 0) __threadfence();
    __syncthreads();
    if (tid < BB * 16) {
        const int bb = tid >> 4, qq = tid & 15;
        double acc64 = 0.0;
        for (int bx = 0; bx < 16; ++bx) {
            float acc32 = 0.f;
#pragma unroll
            for (int ww = 0; ww < 8; ++ww)
                acc32 += g_wsum[bb][bx * 8 + ww][qq];
            acc64 += (double)acc32;
        }
        sums[bb][qq] = acc64;
    }
    __syncthreads();
    if (tid < BB) kabsch_sums(sums[tid], Rsh[tid]);
    __syncthreads();

    if (tid < BB * 12) {
        const int bb = tid / 12, qq = tid % 12;
        const int i = qq / 4, jj = qq % 4;
        float val = (jj < 3) ? Rsh[bb][3 * i + jj] : Rsh[bb][9 + i];
        out[bb * 12 + i * 4 + jj] = val;
    }

    if (tid == 0) {
        g_gen = 0u; g_fincnt = 0u;
        g_momcntB[0] = 0u; g_momcntB[1] = 0u; g_momcntB[2] = 0u; g_momcntB[3] = 0u;
    }
}

// ---------------------------------------------------------------------------
extern "C" void kernel_launch(void* const* d_in, const int* in_sizes, int n_in,
                              void* d_out, int out_size) {
    const float* source = (const float*)d_in[0];
    const float* target = (const float*)d_in[1];
    float*       out    = (float*)d_out;

    const int smem_bytes = (NPAIRS * 8 + NQG * SRCB + SRCB * 3 + SRCB * 3 + 12) * 4
                         + 64;

    cudaFuncSetAttribute(icp_kernel,
                         cudaFuncAttributeMaxDynamicSharedMemorySize, smem_bytes);

    icp_kernel<<<NBLK, TPB, smem_bytes>>>(source, target, out);
}

// round 9
// speedup vs baseline: 1.2549x; 1.2549x over previous
#include <cuda_runtime.h>
#include <math.h>

// Problem constants
#define BB        4
#define NPTS      4096
#define MPTS      4096
#define TPB       512
#define SRCB      128               // sources per block
#define PARTS     8                 // target parts
#define BLK_PER_B 32                // blocks per batch
#define NBLK      (BB * BLK_PER_B)  // 128 blocks total, 1 per SM
#define NPAIRS    (MPTS / 2)        // 2048 target pairs per batch
#define PPP       (NPAIRS / PARTS)  // 256 pairs per part
#define GRPS      8                 // groups per part
#define GP        (PPP / GRPS)      // 32 pairs per group
#define NQG       (PARTS * GRPS)    // 64 (part,group) cells per source
#define ICP_STEPS 16
#define ICP_TOL   1e-6

// ---------------------------------------------------------------------------
// Device-global state. Counters monotonic within a launch, reset by the final
// block -> replay-clean for CUDA graphs.
// ---------------------------------------------------------------------------
__device__ float    g_wsum[BB][128][16];
__device__ float    g_Rt[BB][12];
__device__ double   g_errlast[BB];
__device__ int      g_done;
__device__ unsigned g_gen;
__device__ unsigned g_momcntB[BB];
__device__ unsigned g_fincnt;

// ---------------------------------------------------------------------------
__device__ __forceinline__ void xform(const float* Mtx,
                                      float px, float py, float pz,
                                      float& qx, float& qy, float& qz) {
    qx = fmaf(Mtx[0], px, fmaf(Mtx[1], py, fmaf(Mtx[2], pz, Mtx[9])));
    qy = fmaf(Mtx[3], px, fmaf(Mtx[4], py, fmaf(Mtx[5], pz, Mtx[10])));
    qz = fmaf(Mtx[6], px, fmaf(Mtx[7], py, fmaf(Mtx[8], pz, Mtx[11])));
}

// packed f32x2 helpers (per-half rounding identical to scalar FFMA)
__device__ __forceinline__ unsigned long long pk2(float v) {
    unsigned long long r;
    asm("mov.b64 %0, {%1, %1};" : "=l"(r) : "f"(v));
    return r;
}
__device__ __forceinline__ unsigned long long fma2(unsigned long long a,
                                                   unsigned long long b,
                                                   unsigned long long c) {
    unsigned long long d;
    asm("fma.rn.f32x2 %0, %1, %2, %3;" : "=l"(d) : "l"(a), "l"(b), "l"(c));
    return d;
}
__device__ __forceinline__ void upk2(unsigned long long v, float& lo, float& hi) {
    asm("mov.b64 {%0, %1}, %2;" : "=f"(lo), "=f"(hi) : "l"(v));
}

// ---------------------------------------------------------------------------
// Kabsch from accumulated sums (identical arithmetic to R2-R8).
// ---------------------------------------------------------------------------
__device__ void kabsch_sums(const double* S, float* Rt) {
    const double invN = 1.0 / (double)NPTS;
    double cs[3] = { S[0] * invN, S[1] * invN, S[2] * invN };
    double ct[3] = { S[3] * invN, S[4] * invN, S[5] * invN };

    float H[3][3];
    for (int i = 0; i < 3; ++i)
        for (int j = 0; j < 3; ++j)
            H[i][j] = (float)(S[6 + 3 * i + j] - (double)NPTS * cs[i] * ct[j]);

    float A[3][3];
    for (int i = 0; i < 3; ++i)
        for (int j = 0; j < 3; ++j)
            A[i][j] = H[0][i] * H[0][j] + H[1][i] * H[1][j] + H[2][i] * H[2][j];

    float V[3][3] = { {1,0,0},{0,1,0},{0,0,1} };
    const float diagmag = fabsf(A[0][0]) + fabsf(A[1][1]) + fabsf(A[2][2]);
    const float offeps  = diagmag * 1e-9f;
    for (int sweep = 0; sweep < 8; ++sweep) {
        const float off = fabsf(A[0][1]) + fabsf(A[0][2]) + fabsf(A[1][2]);
        if (off <= offeps) break;
        for (int pq = 0; pq < 3; ++pq) {
            const int p = (pq == 2) ? 1 : 0;
            const int q = (pq == 0) ? 1 : 2;
            const float apq = A[p][q];
            if (fabsf(apq) <= 0.0f) continue;
            const float theta = (A[q][q] - A[p][p]) / (2.0f * apq);
            const float tt = ((theta >= 0.0f) ? 1.0f : -1.0f) /
                             (fabsf(theta) + sqrtf(theta * theta + 1.0f));
            const float c = rsqrtf(tt * tt + 1.0f);
            const float s = tt * c;
            for (int k = 0; k < 3; ++k) { float a1 = A[p][k], a2 = A[q][k];
                A[p][k] = c * a1 - s * a2; A[q][k] = s * a1 + c * a2; }
            for (int k = 0; k < 3; ++k) { float a1 = A[k][p], a2 = A[k][q];
                A[k][p] = c * a1 - s * a2; A[k][q] = s * a1 + c * a2; }
            for (int k = 0; k < 3; ++k) { float v1 = V[k][p], v2 = V[k][q];
                V[k][p] = c * v1 - s * v2; V[k][q] = s * v1 + c * v2; }
        }
    }

    int id[3] = { 0, 1, 2 };
    float w[3] = { A[0][0], A[1][1], A[2][2] };
    if (w[id[0]] < w[id[1]]) { int t0 = id[0]; id[0] = id[1]; id[1] = t0; }
    if (w[id[0]] < w[id[2]]) { int t0 = id[0]; id[0] = id[2]; id[2] = t0; }
    if (w[id[1]] < w[id[2]]) { int t0 = id[1]; id[1] = id[2]; id[2] = t0; }

    float v1[3], v2[3], v3[3];
    for (int k = 0; k < 3; ++k) { v1[k] = V[k][id[0]]; v2[k] = V[k][id[1]]; v3[k] = V[k][id[2]]; }

    float u1[3], u2[3], u3[3];
    for (int i = 0; i < 3; ++i) u1[i] = H[i][0] * v1[0] + H[i][1] * v1[1] + H[i][2] * v1[2];
    {
        float n1 = u1[0]*u1[0] + u1[1]*u1[1] + u1[2]*u1[2];
        float r = (n1 > 0.0f) ? rsqrtf(n1) : 0.0f;
        u1[0] *= r; u1[1] *= r; u1[2] *= r;
    }
    for (int i = 0; i < 3; ++i) u2[i] = H[i][0] * v2[0] + H[i][1] * v2[1] + H[i][2] * v2[2];
    {
        float pr = u1[0]*u2[0] + u1[1]*u2[1] + u1[2]*u2[2];
        u2[0] -= pr * u1[0]; u2[1] -= pr * u1[1]; u2[2] -= pr * u1[2];
        float n2 = u2[0]*u2[0] + u2[1]*u2[1] + u2[2]*u2[2];
        float r = (n2 > 0.0f) ? rsqrtf(n2) : 0.0f;
        u2[0] *= r; u2[1] *= r; u2[2] *= r;
    }
    u3[0] = u1[1]*u2[2] - u1[2]*u2[1];
    u3[1] = u1[2]*u2[0] - u1[0]*u2[2];
    u3[2] = u1[0]*u2[1] - u1[1]*u2[0];

    const float d =
        v1[0] * (v2[1]*v3[2] - v2[2]*v3[1]) -
        v1[1] * (v2[0]*v3[2] - v2[2]*v3[0]) +
        v1[2] * (v2[0]*v3[1] - v2[1]*v3[0]);

    float R[9];
    for (int i = 0; i < 3; ++i)
        for (int j = 0; j < 3; ++j)
            R[3 * i + j] = v1[i]*u1[j] + v2[i]*u2[j] + d * v3[i]*u3[j];
    for (int k = 0; k < 9; ++k) Rt[k] = R[k];
    for (int i = 0; i < 3; ++i)
        Rt[9 + i] = (float)ct[i] - (R[3*i]*(float)cs[0] + R[3*i+1]*(float)cs[1]
                                    + R[3*i+2]*(float)cs[2]);
}

// ---------------------------------------------------------------------------
// Warp shfl reduction identical to the original block_reduce16 intra-warp
// stage; lane0 writes its warp row to g_wsum. Caller: threads 0..127 only.
// ---------------------------------------------------------------------------
__device__ __forceinline__ void warp_reduce16_store(const float v[16],
                                                    int b, int row) {
    const int lane = threadIdx.x & 31;
#pragma unroll
    for (int q = 0; q < 16; ++q) {
        float r = v[q];
#pragma unroll
        for (int o = 16; o > 0; o >>= 1) r += __shfl_down_sync(0xffffffffu, r, o);
        if (lane == 0) g_wsum[b][row][q] = r;
    }
}

// ---------------------------------------------------------------------------
// Persistent fused ICP kernel: 128 blocks x 512 threads (1 block/SM).
// 16 warps: sh = w>>3 picks source half, q = w&7 picks target part.
// Each LANE handles TWO sources (srcA = sh*64+lane, srcB = srcA+32):
// every loaded target pair feeds both distance chains -> LDS per step halved.
// Phase A: min-VALUE-only (FMNMX). Phase B: exact index recovery by rescan.
// ---------------------------------------------------------------------------
extern __shared__ __align__(16) float smem_dyn[];

__global__ void __launch_bounds__(TPB, 1)
icp_kernel(const float* __restrict__ src, const float* __restrict__ tgt,
           float* __restrict__ out) {
    // dynamic smem layout
    float* tgP   = smem_dyn;                       // 2048 pairs * 8 f = 64KB
    float* gmins = tgP + NPAIRS * 8;               // 64 * 128 f = 32KB
    float* srcP  = gmins + NQG * SRCB;             // 128*3
    float* mw    = srcP + SRCB * 3;                // 128*3
    float* RtSh  = mw + SRCB * 3;                  // 12

    __shared__ double sums[BB][16];
    __shared__ float  Rsh[BB][12];
    __shared__ int    convf[BB];
    __shared__ int    s_isfin;
    __shared__ int    s_done;

    const int tid  = threadIdx.x;
    const int w    = tid >> 5;                 // warp 0..15
    const int lane = tid & 31;
    const int sh   = w >> 3;                   // source half 0..1
    const int q    = w & 7;                    // target part 0..7
    const int srcA = sh * 64 + lane;           // first source of this lane
    const int srcB = srcA + 32;                // second source of this lane
    const int b    = blockIdx.x >> 5;          // batch
    const int blk2 = blockIdx.x & 31;          // 128-source slice

    // ---- stage full target set; pair p: [x0 x1 y0 y1 z0 z1 w0 w1]
    {
        const float* T = tgt + (size_t)b * MPTS * 3;
        for (int k = tid; k < MPTS; k += TPB) {
            float x = T[3 * k], y = T[3 * k + 1], z = T[3 * k + 2];
            float ww = fmaf(x, x, fmaf(y, y, z * z));
            int p = k >> 1, h = k & 1;
            tgP[p * 8 + 0 + h] = x;
            tgP[p * 8 + 2 + h] = y;
            tgP[p * 8 + 4 + h] = z;
            tgP[p * 8 + 6 + h] = ww;
        }
    }
    if (tid < SRCB * 3) {
        srcP[tid] = src[(size_t)(b * NPTS + blk2 * SRCB) * 3 + tid];
    }
    __syncthreads();

    const ulonglong2* tg2 = (const ulonglong2*)tgP;   // pair p = tg2[2p], tg2[2p+1]

    for (int k = 0; k < ICP_STEPS; ++k) {
        // ---- wait for generation k, stage transform
        if (k > 0) {
            if (tid == 0) {
                while (*(volatile unsigned*)&g_gen < (unsigned)k) __nanosleep(32);
                __threadfence();
            }
            __syncthreads();
            if (tid < 12) RtSh[tid] = g_Rt[b][tid];
            __syncthreads();
        }

        // ---- transform this lane's two source points (identity at k==0)
        float wxa, wya, wza, wxb, wyb, wzb;
        {
            const float pxa = srcP[3 * srcA], pya = srcP[3 * srcA + 1], pza = srcP[3 * srcA + 2];
            const float pxb = srcP[3 * srcB], pyb = srcP[3 * srcB + 1], pzb = srcP[3 * srcB + 2];
            if (k == 0) {
                const float I[12] = {1.f,0.f,0.f, 0.f,1.f,0.f, 0.f,0.f,1.f, 0.f,0.f,0.f};
                xform(I, pxa, pya, pza, wxa, wya, wza);
                xform(I, pxb, pyb, pzb, wxb, wyb, wzb);
            } else {
                xform(RtSh, pxa, pya, pza, wxa, wya, wza);
                xform(RtSh, pxb, pyb, pzb, wxb, wyb, wzb);
            }
        }

        // ================= Phase A: min-value-only scan, 2 sources ==========
        {
            const unsigned long long axa = pk2(-2.f * wxa);
            const unsigned long long aya = pk2(-2.f * wya);
            const unsigned long long aza = pk2(-2.f * wza);
            const unsigned long long axb = pk2(-2.f * wxb);
            const unsigned long long ayb = pk2(-2.f * wyb);
            const unsigned long long azb = pk2(-2.f * wzb);
            const int pbase = q * PPP;

#pragma unroll
            for (int grp = 0; grp < GRPS; ++grp) {
                const int gp = pbase + grp * GP;
                float gmEa = 3.4e38f, gmOa = 3.4e38f;
                float gmEb = 3.4e38f, gmOb = 3.4e38f;
#pragma unroll 8
                for (int i = 0; i < GP; ++i) {
                    const ulonglong2 A  = tg2[2 * (gp + i)];
                    const ulonglong2 Bv = tg2[2 * (gp + i) + 1];
                    unsigned long long sA =
                        fma2(axa, A.x, fma2(aya, A.y, fma2(aza, Bv.x, Bv.y)));
                    unsigned long long sB =
                        fma2(axb, A.x, fma2(ayb, A.y, fma2(azb, Bv.x, Bv.y)));
                    float ea, oa, eb, ob;
                    upk2(sA, ea, oa);
                    upk2(sB, eb, ob);
                    gmEa = fminf(gmEa, ea);
                    gmOa = fminf(gmOa, oa);
                    gmEb = fminf(gmEb, eb);
                    gmOb = fminf(gmOb, ob);
                }
                gmins[(q * GRPS + grp) * SRCB + srcA] = fminf(gmEa, gmOa);
                gmins[(q * GRPS + grp) * SRCB + srcB] = fminf(gmEb, gmOb);
            }
        }
        if (q == 0) {   // one copy of the transformed points per source
            mw[3 * srcA] = wxa; mw[3 * srcA + 1] = wya; mw[3 * srcA + 2] = wza;
            mw[3 * srcB] = wxb; mw[3 * srcB + 1] = wyb; mw[3 * srcB + 2] = wzb;
        }
        __syncthreads();

        // ============ Phase B + moments (threads 0..127, src = tid) ========
        if (tid < SRCB) {
            // global min over 64 group mins (exact; identical to full scan)
            float m = gmins[tid];
#pragma unroll 8
            for (int t = 1; t < NQG; ++t) m = fminf(m, gmins[t * SRCB + tid]);

            // first (ascending-j) group attaining m
            int qg = 0;
#pragma unroll 8
            for (int t = NQG - 1; t >= 0; --t)
                if (gmins[t * SRCB + tid] == m) qg = t;

            // rescan that group's 32 pairs, identical arithmetic, smallest j
            const float mx = mw[3 * tid], my = mw[3 * tid + 1], mz = mw[3 * tid + 2];
            const unsigned long long ax2 = pk2(-2.f * mx);
            const unsigned long long ay2 = pk2(-2.f * my);
            const unsigned long long az2 = pk2(-2.f * mz);
            const int pstart = qg * GP;

            int jb = 0xFFFF;
#pragma unroll 4
            for (int i = 0; i < GP; ++i) {
                const ulonglong2 A  = tg2[2 * (pstart + i)];
                const ulonglong2 Bv = tg2[2 * (pstart + i) + 1];
                unsigned long long s01 =
                    fma2(ax2, A.x, fma2(ay2, A.y, fma2(az2, Bv.x, Bv.y)));
                float e, o;
                upk2(s01, e, o);
                if (e == m) jb = min(jb, 2 * (pstart + i));
                if (o == m) jb = min(jb, 2 * (pstart + i) + 1);
            }
            const unsigned j = (unsigned)jb;
            const float    s = m;

            const float a2v = fmaf(mx, mx, fmaf(my, my, mz * mz));
            const float d2  = fmaxf(s + a2v, 0.f);
            const float ec  = sqrtf(d2);

            const unsigned p = j >> 1, h = j & 1;
            const float tx = tgP[p * 8 + 0 + h];
            const float ty = tgP[p * 8 + 2 + h];
            const float tz = tgP[p * 8 + 4 + h];

            const float v[16] = { mx, my, mz, tx, ty, tz,
                                  mx * tx, mx * ty, mx * tz,
                                  my * tx, my * ty, my * tz,
                                  mz * tx, mz * ty, mz * tz, ec };
            warp_reduce16_store(v, b, blk2 * 4 + (tid >> 5));

            srcP[3 * tid] = mx; srcP[3 * tid + 1] = my; srcP[3 * tid + 2] = mz;
        }
        __threadfence();
        __syncthreads();

        // ---- two-level arrival: per-batch counter, then tiny global counter
        if (tid == 0) {
            s_isfin = 0;
            unsigned oldb = atomicAdd(&g_momcntB[b], 1u);
            if (oldb == (unsigned)(BLK_PER_B * (k + 1) - 1)) {
                unsigned oldf = atomicAdd(&g_fincnt, 1u);
                s_isfin = (oldf == (unsigned)(BB * (k + 1) - 1)) ? 1 : 0;
            }
        }
        __syncthreads();

        if (s_isfin) {
            if (tid == 0) __threadfence();
            __syncthreads();
            if (tid < BB * 16) {
                const int bb = tid >> 4, qq = tid & 15;
                double acc64 = 0.0;
                for (int bx = 0; bx < 16; ++bx) {
                    float acc32 = 0.f;
#pragma unroll
                    for (int ww = 0; ww < 8; ++ww)
                        acc32 += g_wsum[bb][bx * 8 + ww][qq];
                    acc64 += (double)acc32;
                }
                sums[bb][qq] = acc64;
            }
            __syncthreads();

            double errnew = 0.0;
            if (tid < BB) {
                errnew = sums[tid][15] / (double)NPTS;
                const double errlast = (k == 0) ? 0.0 : g_errlast[tid];
                convf[tid] = (fabs(errnew - errlast) < ICP_TOL) ? 1 : 0;
                kabsch_sums(sums[tid], Rsh[tid]);
            }
            __syncthreads();
            if (tid == 0) {
                const int all  = convf[0] & convf[1] & convf[2] & convf[3];
                const int prev = (k == 0) ? 0 : g_done;
                s_done = prev | all;
                g_done = s_done;
            }
            __syncthreads();
            if (tid < BB) {
                if (!s_done) {
                    g_errlast[tid] = errnew;
                    for (int qq = 0; qq < 12; ++qq) g_Rt[tid][qq] = Rsh[tid][qq];
                } else {
                    for (int qq = 0; qq < 12; ++qq)
                        g_Rt[tid][qq] = (qq == 0 || qq == 4 || qq == 8) ? 1.f : 0.f;
                }
            }
            __threadfence();
            __syncthreads();
            if (tid == 0) atomicExch(&g_gen, (unsigned)(k + 1));   // release
        }
    }

    // ======================= FINAL kabsch(source, temporal) ==================
    if (tid == 0) {
        while (*(volatile unsigned*)&g_gen < (unsigned)ICP_STEPS) __nanosleep(32);
        __threadfence();
    }
    __syncthreads();
    if (tid < 12) RtSh[tid] = g_Rt[b][tid];
    __syncthreads();

    if (tid < SRCB) {
        const float px = srcP[3 * tid], py = srcP[3 * tid + 1], pz = srcP[3 * tid + 2];
        float wx, wy, wz;
        xform(RtSh, px, py, pz, wx, wy, wz);

        const float sx = src[3 * (b * NPTS + blk2 * SRCB + tid)];
        const float sy = src[3 * (b * NPTS + blk2 * SRCB + tid) + 1];
        const float sz = src[3 * (b * NPTS + blk2 * SRCB + tid) + 2];

        const float v[16] = { sx, sy, sz, wx, wy, wz,
                              sx * wx, sx * wy, sx * wz,
                              sy * wx, sy * wy, sy * wz,
                              sz * wx, sz * wy, sz * wz, 0.f };
        warp_reduce16_store(v, b, blk2 * 4 + (tid >> 5));
    }
    __threadfence();
    __syncthreads();
    if (tid == 0) {
        s_isfin = 0;
        unsigned oldb = atomicAdd(&g_momcntB[b], 1u);
        if (oldb == (unsigned)(BLK_PER_B * (ICP_STEPS + 1) - 1)) {
            unsigned oldf = atomicAdd(&g_fincnt, 1u);
            s_isfin = (oldf == (unsigned)(BB * (ICP_STEPS + 1) - 1)) ? 1 : 0;
        }
    }
    __syncthreads();
    if (!s_isfin) return;

    // ---- last block: final kabsch, output, counter reset for next replay
    if (tid == 0) __threadfence();
    __syncthreads();
    if (tid < BB * 16) {
        const int bb = tid >> 4, qq = tid & 15;
        double acc64 = 0.0;
        for (int bx = 0; bx < 16; ++bx) {
            float acc32 = 0.f;
#pragma unroll
            for (int ww = 0; ww < 8; ++ww)
                acc32 += g_wsum[bb][bx * 8 + ww][qq];
            acc64 += (double)acc32;
        }
        sums[bb][qq] = acc64;
    }
    __syncthreads();
    if (tid < BB) kabsch_sums(sums[tid], Rsh[tid]);
    __syncthreads();

    if (tid < BB * 12) {
        const int bb = tid / 12, qq = tid % 12;
        const int i = qq / 4, jj = qq % 4;
        float val = (jj < 3) ? Rsh[bb][3 * i + jj] : Rsh[bb][9 + i];
        out[bb * 12 + i * 4 + jj] = val;
    }

    if (tid == 0) {
        g_gen = 0u; g_fincnt = 0u;
        g_momcntB[0] = 0u; g_momcntB[1] = 0u; g_momcntB[2] = 0u; g_momcntB[3] = 0u;
    }
}

// ---------------------------------------------------------------------------
extern "C" void kernel_launch(void* const* d_in, const int* in_sizes, int n_in,
                              void* d_out, int out_size) {
    const float* source = (const float*)d_in[0];
    const float* target = (const float*)d_in[1];
    float*       out    = (float*)d_out;

    const int smem_bytes = (NPAIRS * 8 + NQG * SRCB + SRCB * 3 + SRCB * 3 + 12) * 4
                         + 64;

    cudaFuncSetAttribute(icp_kernel,
                         cudaFuncAttributeMaxDynamicSharedMemorySize, smem_bytes);

    icp_kernel<<<NBLK, TPB, smem_bytes>>>(source, target, out);
}

// round 10
// speedup vs baseline: 1.2634x; 1.0068x over previous
#include <cuda_runtime.h>
#include <math.h>

// Problem constants
#define BB        4
#define NPTS      4096
#define MPTS      4096
#define TPB       512
#define SRCB      128               // sources per block
#define PARTS     16                // target parts (one per warp)
#define BLK_PER_B 32                // blocks per batch
#define NBLK      (BB * BLK_PER_B)  // 128 blocks total, 1 per SM
#define NPAIRS    (MPTS / 2)        // 2048 target pairs per batch
#define PPP       (NPAIRS / PARTS)  // 128 pairs per part
#define GRPS      4                 // groups per part
#define GP        (PPP / GRPS)      // 32 pairs per group
#define NQG       (PARTS * GRPS)    // 64 cells; cell t covers pairs [32t,32t+32)
#define ICP_STEPS 16
#define ICP_TOL   1e-6

// ---------------------------------------------------------------------------
// Device-global state. Counters monotonic within a launch, reset by the final
// block -> replay-clean for CUDA graphs.
// ---------------------------------------------------------------------------
__device__ float    g_wsum[BB][128][16];
__device__ float    g_Rt[BB][12];
__device__ double   g_errlast[BB];
__device__ int      g_done;
__device__ unsigned g_gen;
__device__ unsigned g_momcntB[BB];
__device__ unsigned g_fincnt;

// ---------------------------------------------------------------------------
__device__ __forceinline__ void xform(const float* Mtx,
                                      float px, float py, float pz,
                                      float& qx, float& qy, float& qz) {
    qx = fmaf(Mtx[0], px, fmaf(Mtx[1], py, fmaf(Mtx[2], pz, Mtx[9])));
    qy = fmaf(Mtx[3], px, fmaf(Mtx[4], py, fmaf(Mtx[5], pz, Mtx[10])));
    qz = fmaf(Mtx[6], px, fmaf(Mtx[7], py, fmaf(Mtx[8], pz, Mtx[11])));
}

// packed f32x2 helpers (per-half rounding identical to scalar FFMA)
__device__ __forceinline__ unsigned long long pk2(float v) {
    unsigned long long r;
    asm("mov.b64 %0, {%1, %1};" : "=l"(r) : "f"(v));
    return r;
}
__device__ __forceinline__ unsigned long long fma2(unsigned long long a,
                                                   unsigned long long b,
                                                   unsigned long long c) {
    unsigned long long d;
    asm("fma.rn.f32x2 %0, %1, %2, %3;" : "=l"(d) : "l"(a), "l"(b), "l"(c));
    return d;
}
__device__ __forceinline__ void upk2(unsigned long long v, float& lo, float& hi) {
    asm("mov.b64 {%0, %1}, %2;" : "=f"(lo), "=f"(hi) : "l"(v));
}

// ---------------------------------------------------------------------------
// Kabsch from accumulated sums (identical arithmetic to R2-R9).
// ---------------------------------------------------------------------------
__device__ void kabsch_sums(const double* S, float* Rt) {
    const double invN = 1.0 / (double)NPTS;
    double cs[3] = { S[0] * invN, S[1] * invN, S[2] * invN };
    double ct[3] = { S[3] * invN, S[4] * invN, S[5] * invN };

    float H[3][3];
    for (int i = 0; i < 3; ++i)
        for (int j = 0; j < 3; ++j)
            H[i][j] = (float)(S[6 + 3 * i + j] - (double)NPTS * cs[i] * ct[j]);

    float A[3][3];
    for (int i = 0; i < 3; ++i)
        for (int j = 0; j < 3; ++j)
            A[i][j] = H[0][i] * H[0][j] + H[1][i] * H[1][j] + H[2][i] * H[2][j];

    float V[3][3] = { {1,0,0},{0,1,0},{0,0,1} };
    const float diagmag = fabsf(A[0][0]) + fabsf(A[1][1]) + fabsf(A[2][2]);
    const float offeps  = diagmag * 1e-9f;
    for (int sweep = 0; sweep < 8; ++sweep) {
        const float off = fabsf(A[0][1]) + fabsf(A[0][2]) + fabsf(A[1][2]);
        if (off <= offeps) break;
        for (int pq = 0; pq < 3; ++pq) {
            const int p = (pq == 2) ? 1 : 0;
            const int q = (pq == 0) ? 1 : 2;
            const float apq = A[p][q];
            if (fabsf(apq) <= 0.0f) continue;
            const float theta = (A[q][q] - A[p][p]) / (2.0f * apq);
            const float tt = ((theta >= 0.0f) ? 1.0f : -1.0f) /
                             (fabsf(theta) + sqrtf(theta * theta + 1.0f));
            const float c = rsqrtf(tt * tt + 1.0f);
            const float s = tt * c;
            for (int k = 0; k < 3; ++k) { float a1 = A[p][k], a2 = A[q][k];
                A[p][k] = c * a1 - s * a2; A[q][k] = s * a1 + c * a2; }
            for (int k = 0; k < 3; ++k) { float a1 = A[k][p], a2 = A[k][q];
                A[k][p] = c * a1 - s * a2; A[k][q] = s * a1 + c * a2; }
            for (int k = 0; k < 3; ++k) { float v1 = V[k][p], v2 = V[k][q];
                V[k][p] = c * v1 - s * v2; V[k][q] = s * v1 + c * v2; }
        }
    }

    int id[3] = { 0, 1, 2 };
    float w[3] = { A[0][0], A[1][1], A[2][2] };
    if (w[id[0]] < w[id[1]]) { int t0 = id[0]; id[0] = id[1]; id[1] = t0; }
    if (w[id[0]] < w[id[2]]) { int t0 = id[0]; id[0] = id[2]; id[2] = t0; }
    if (w[id[1]] < w[id[2]]) { int t0 = id[1]; id[1] = id[2]; id[2] = t0; }

    float v1[3], v2[3], v3[3];
    for (int k = 0; k < 3; ++k) { v1[k] = V[k][id[0]]; v2[k] = V[k][id[1]]; v3[k] = V[k][id[2]]; }

    float u1[3], u2[3], u3[3];
    for (int i = 0; i < 3; ++i) u1[i] = H[i][0] * v1[0] + H[i][1] * v1[1] + H[i][2] * v1[2];
    {
        float n1 = u1[0]*u1[0] + u1[1]*u1[1] + u1[2]*u1[2];
        float r = (n1 > 0.0f) ? rsqrtf(n1) : 0.0f;
        u1[0] *= r; u1[1] *= r; u1[2] *= r;
    }
    for (int i = 0; i < 3; ++i) u2[i] = H[i][0] * v2[0] + H[i][1] * v2[1] + H[i][2] * v2[2];
    {
        float pr = u1[0]*u2[0] + u1[1]*u2[1] + u1[2]*u2[2];
        u2[0] -= pr * u1[0]; u2[1] -= pr * u1[1]; u2[2] -= pr * u1[2];
        float n2 = u2[0]*u2[0] + u2[1]*u2[1] + u2[2]*u2[2];
        float r = (n2 > 0.0f) ? rsqrtf(n2) : 0.0f;
        u2[0] *= r; u2[1] *= r; u2[2] *= r;
    }
    u3[0] = u1[1]*u2[2] - u1[2]*u2[1];
    u3[1] = u1[2]*u2[0] - u1[0]*u2[2];
    u3[2] = u1[0]*u2[1] - u1[1]*u2[0];

    const float d =
        v1[0] * (v2[1]*v3[2] - v2[2]*v3[1]) -
        v1[1] * (v2[0]*v3[2] - v2[2]*v3[0]) +
        v1[2] * (v2[0]*v3[1] - v2[1]*v3[0]);

    float R[9];
    for (int i = 0; i < 3; ++i)
        for (int j = 0; j < 3; ++j)
            R[3 * i + j] = v1[i]*u1[j] + v2[i]*u2[j] + d * v3[i]*u3[j];
    for (int k = 0; k < 9; ++k) Rt[k] = R[k];
    for (int i = 0; i < 3; ++i)
        Rt[9 + i] = (float)ct[i] - (R[3*i]*(float)cs[0] + R[3*i+1]*(float)cs[1]
                                    + R[3*i+2]*(float)cs[2]);
}

// ---------------------------------------------------------------------------
// Warp shfl reduction identical to the original block_reduce16 intra-warp
// stage; lane0 writes its warp row to g_wsum. Caller: threads 0..127 only.
// ---------------------------------------------------------------------------
__device__ __forceinline__ void warp_reduce16_store(const float v[16],
                                                    int b, int row) {
    const int lane = threadIdx.x & 31;
#pragma unroll
    for (int q = 0; q < 16; ++q) {
        float r = v[q];
#pragma unroll
        for (int o = 16; o > 0; o >>= 1) r += __shfl_down_sync(0xffffffffu, r, o);
        if (lane == 0) g_wsum[b][row][q] = r;
    }
}

// ---------------------------------------------------------------------------
// Persistent fused ICP kernel: 128 blocks x 512 threads (1 block/SM).
// Warp w = target part (16 parts x 128 pairs). Each LANE handles FOUR
// sources {lane, lane+32, lane+64, lane+96}: every loaded target pair feeds
// four distance chains -> LDS per step halved again vs R9, 8 indep FMNMX
// chains + 12 indep FMA2 per load for ILP.
// Phase A: min-VALUE-only (FMNMX). Phase B: exact index recovery by rescan.
// ---------------------------------------------------------------------------
extern __shared__ __align__(16) float smem_dyn[];

__global__ void __launch_bounds__(TPB, 1)
icp_kernel(const float* __restrict__ src, const float* __restrict__ tgt,
           float* __restrict__ out) {
    // dynamic smem layout
    float* tgP   = smem_dyn;                       // 2048 pairs * 8 f = 64KB
    float* gmins = tgP + NPAIRS * 8;               // 64 * 128 f = 32KB
    float* srcP  = gmins + NQG * SRCB;             // 128*3
    float* mw    = srcP + SRCB * 3;                // 128*3
    float* RtSh  = mw + SRCB * 3;                  // 12

    __shared__ double sums[BB][16];
    __shared__ float  Rsh[BB][12];
    __shared__ int    convf[BB];
    __shared__ int    s_isfin;
    __shared__ int    s_done;

    const int tid  = threadIdx.x;
    const int w    = tid >> 5;                 // warp 0..15 == target part
    const int lane = tid & 31;
    const int b    = blockIdx.x >> 5;          // batch
    const int blk2 = blockIdx.x & 31;          // 128-source slice

    // this lane's four sources
    const int s0 = lane, s1 = lane + 32, s2 = lane + 64, s3 = lane + 96;

    // ---- stage full target set; pair p: [x0 x1 y0 y1 z0 z1 w0 w1]
    {
        const float* T = tgt + (size_t)b * MPTS * 3;
        for (int k = tid; k < MPTS; k += TPB) {
            float x = T[3 * k], y = T[3 * k + 1], z = T[3 * k + 2];
            float ww = fmaf(x, x, fmaf(y, y, z * z));
            int p = k >> 1, h = k & 1;
            tgP[p * 8 + 0 + h] = x;
            tgP[p * 8 + 2 + h] = y;
            tgP[p * 8 + 4 + h] = z;
            tgP[p * 8 + 6 + h] = ww;
        }
    }
    if (tid < SRCB * 3) {
        srcP[tid] = src[(size_t)(b * NPTS + blk2 * SRCB) * 3 + tid];
    }
    __syncthreads();

    const ulonglong2* tg2 = (const ulonglong2*)tgP;   // pair p = tg2[2p], tg2[2p+1]

    for (int k = 0; k < ICP_STEPS; ++k) {
        // ---- wait for generation k, stage transform
        if (k > 0) {
            if (tid == 0) {
                while (*(volatile unsigned*)&g_gen < (unsigned)k) __nanosleep(32);
                __threadfence();
            }
            __syncthreads();
            if (tid < 12) RtSh[tid] = g_Rt[b][tid];
            __syncthreads();
        }

        // ---- transform this lane's four source points (identity at k==0)
        float wx[4], wy[4], wz[4];
        {
            const int ss[4] = { s0, s1, s2, s3 };
#pragma unroll
            for (int t = 0; t < 4; ++t) {
                const float px = srcP[3 * ss[t]], py = srcP[3 * ss[t] + 1],
                            pz = srcP[3 * ss[t] + 2];
                if (k == 0) {
                    const float I[12] = {1.f,0.f,0.f, 0.f,1.f,0.f, 0.f,0.f,1.f,
                                         0.f,0.f,0.f};
                    xform(I, px, py, pz, wx[t], wy[t], wz[t]);
                } else {
                    xform(RtSh, px, py, pz, wx[t], wy[t], wz[t]);
                }
            }
        }

        // ================= Phase A: min-value-only scan, 4 sources ==========
        {
            unsigned long long ax[4], ay[4], az[4];
#pragma unroll
            for (int t = 0; t < 4; ++t) {
                ax[t] = pk2(-2.f * wx[t]);
                ay[t] = pk2(-2.f * wy[t]);
                az[t] = pk2(-2.f * wz[t]);
            }
            const int pbase = w * PPP;

#pragma unroll
            for (int grp = 0; grp < GRPS; ++grp) {
                const int gp = pbase + grp * GP;
                float gmE[4] = { 3.4e38f, 3.4e38f, 3.4e38f, 3.4e38f };
                float gmO[4] = { 3.4e38f, 3.4e38f, 3.4e38f, 3.4e38f };
#pragma unroll 4
                for (int i = 0; i < GP; ++i) {
                    const ulonglong2 A  = tg2[2 * (gp + i)];
                    const ulonglong2 Bv = tg2[2 * (gp + i) + 1];
#pragma unroll
                    for (int t = 0; t < 4; ++t) {
                        unsigned long long s01 =
                            fma2(ax[t], A.x, fma2(ay[t], A.y,
                                 fma2(az[t], Bv.x, Bv.y)));
                        float e, o;
                        upk2(s01, e, o);
                        gmE[t] = fminf(gmE[t], e);
                        gmO[t] = fminf(gmO[t], o);
                    }
                }
                const int cell = (w * GRPS + grp) * SRCB;   // == (32*pstart)/GP
                gmins[cell + s0] = fminf(gmE[0], gmO[0]);
                gmins[cell + s1] = fminf(gmE[1], gmO[1]);
                gmins[cell + s2] = fminf(gmE[2], gmO[2]);
                gmins[cell + s3] = fminf(gmE[3], gmO[3]);
            }
        }
        if (w == 0) {   // one copy of the transformed points per source
            mw[3 * s0] = wx[0]; mw[3 * s0 + 1] = wy[0]; mw[3 * s0 + 2] = wz[0];
            mw[3 * s1] = wx[1]; mw[3 * s1 + 1] = wy[1]; mw[3 * s1 + 2] = wz[1];
            mw[3 * s2] = wx[2]; mw[3 * s2 + 1] = wy[2]; mw[3 * s2 + 2] = wz[2];
            mw[3 * s3] = wx[3]; mw[3 * s3 + 1] = wy[3]; mw[3 * s3 + 2] = wz[3];
        }
        __syncthreads();

        // ============ Phase B + moments (threads 0..127, src = tid) ========
        if (tid < SRCB) {
            // global min over 64 cell mins (exact; identical to full scan)
            float m = gmins[tid];
#pragma unroll 8
            for (int t = 1; t < NQG; ++t) m = fminf(m, gmins[t * SRCB + tid]);

            // first (ascending-j) cell attaining m
            int qg = 0;
#pragma unroll 8
            for (int t = NQG - 1; t >= 0; --t)
                if (gmins[t * SRCB + tid] == m) qg = t;

            // rescan that cell's 32 pairs, identical arithmetic, smallest j
            const float mx = mw[3 * tid], my = mw[3 * tid + 1], mz = mw[3 * tid + 2];
            const unsigned long long ax2 = pk2(-2.f * mx);
            const unsigned long long ay2 = pk2(-2.f * my);
            const unsigned long long az2 = pk2(-2.f * mz);
            const int pstart = qg * GP;   // cell t covers pairs [32t, 32t+32)

            int jb = 0xFFFF;
#pragma unroll 4
            for (int i = 0; i < GP; ++i) {
                const ulonglong2 A  = tg2[2 * (pstart + i)];
                const ulonglong2 Bv = tg2[2 * (pstart + i) + 1];
                unsigned long long s01 =
                    fma2(ax2, A.x, fma2(ay2, A.y, fma2(az2, Bv.x, Bv.y)));
                float e, o;
                upk2(s01, e, o);
                if (e == m) jb = min(jb, 2 * (pstart + i));
                if (o == m) jb = min(jb, 2 * (pstart + i) + 1);
            }
            const unsigned j = (unsigned)jb;
            const float    s = m;

            const float a2v = fmaf(mx, mx, fmaf(my, my, mz * mz));
            const float d2  = fmaxf(s + a2v, 0.f);
            const float ec  = sqrtf(d2);

            const unsigned p = j >> 1, h = j & 1;
            const float tx = tgP[p * 8 + 0 + h];
            const float ty = tgP[p * 8 + 2 + h];
            const float tz = tgP[p * 8 + 4 + h];

            const float v[16] = { mx, my, mz, tx, ty, tz,
                                  mx * tx, mx * ty, mx * tz,
                                  my * tx, my * ty, my * tz,
                                  mz * tx, mz * ty, mz * tz, ec };
            warp_reduce16_store(v, b, blk2 * 4 + (tid >> 5));

            srcP[3 * tid] = mx; srcP[3 * tid + 1] = my; srcP[3 * tid + 2] = mz;
        }
        __threadfence();
        __syncthreads();

        // ---- two-level arrival: per-batch counter, then tiny global counter
        if (tid == 0) {
            s_isfin = 0;
            unsigned oldb = atomicAdd(&g_momcntB[b], 1u);
            if (oldb == (unsigned)(BLK_PER_B * (k + 1) - 1)) {
                unsigned oldf = atomicAdd(&g_fincnt, 1u);
                s_isfin = (oldf == (unsigned)(BB * (k + 1) - 1)) ? 1 : 0;
            }
        }
        __syncthreads();

        if (s_isfin) {
            if (tid == 0) __threadfence();
            __syncthreads();
            if (tid < BB * 16) {
                const int bb = tid >> 4, qq = tid & 15;
                double acc64 = 0.0;
                for (int bx = 0; bx < 16; ++bx) {
                    float acc32 = 0.f;
#pragma unroll
                    for (int ww = 0; ww < 8; ++ww)
                        acc32 += g_wsum[bb][bx * 8 + ww][qq];
                    acc64 += (double)acc32;
                }
                sums[bb][qq] = acc64;
            }
            __syncthreads();

            double errnew = 0.0;
            if (tid < BB) {
                errnew = sums[tid][15] / (double)NPTS;
                const double errlast = (k == 0) ? 0.0 : g_errlast[tid];
                convf[tid] = (fabs(errnew - errlast) < ICP_TOL) ? 1 : 0;
                kabsch_sums(sums[tid], Rsh[tid]);
            }
            __syncthreads();
            if (tid == 0) {
                const int all  = convf[0] & convf[1] & convf[2] & convf[3];
                const int prev = (k == 0) ? 0 : g_done;
                s_done = prev | all;
                g_done = s_done;
            }
            __syncthreads();
            if (tid < BB) {
                if (!s_done) {
                    g_errlast[tid] = errnew;
                    for (int qq = 0; qq < 12; ++qq) g_Rt[tid][qq] = Rsh[tid][qq];
                } else {
                    for (int qq = 0; qq < 12; ++qq)
                        g_Rt[tid][qq] = (qq == 0 || qq == 4 || qq == 8) ? 1.f : 0.f;
                }
            }
            __threadfence();
            __syncthreads();
            if (tid == 0) atomicExch(&g_gen, (unsigned)(k + 1));   // release
        }
    }

    // ======================= FINAL kabsch(source, temporal) ==================
    if (tid == 0) {
        while (*(volatile unsigned*)&g_gen < (unsigned)ICP_STEPS) __nanosleep(32);
        __threadfence();
    }
    __syncthreads();
    if (tid < 12) RtSh[tid] = g_Rt[b][tid];
    __syncthreads();

    if (tid < SRCB) {
        const float px = srcP[3 * tid], py = srcP[3 * tid + 1], pz = srcP[3 * tid + 2];
        float wxf, wyf, wzf;
        xform(RtSh, px, py, pz, wxf, wyf, wzf);

        const float sx = src[3 * (b * NPTS + blk2 * SRCB + tid)];
        const float sy = src[3 * (b * NPTS + blk2 * SRCB + tid) + 1];
        const float sz = src[3 * (b * NPTS + blk2 * SRCB + tid) + 2];

        const float v[16] = { sx, sy, sz, wxf, wyf, wzf,
                              sx * wxf, sx * wyf, sx * wzf,
                              sy * wxf, sy * wyf, sy * wzf,
                              sz * wxf, sz * wyf, sz * wzf, 0.f };
        warp_reduce16_store(v, b, blk2 * 4 + (tid >> 5));
    }
    __threadfence();
    __syncthreads();
    if (tid == 0) {
        s_isfin = 0;
        unsigned oldb = atomicAdd(&g_momcntB[b], 1u);
        if (oldb == (unsigned)(BLK_PER_B * (ICP_STEPS + 1) - 1)) {
            unsigned oldf = atomicAdd(&g_fincnt, 1u);
            s_isfin = (oldf == (unsigned)(BB * (ICP_STEPS + 1) - 1)) ? 1 : 0;
        }
    }
    __syncthreads();
    if (!s_isfin) return;

    // ---- last block: final kabsch, output, counter reset for next replay
    if (tid == 0) __threadfence();
    __syncthreads();
    if (tid < BB * 16) {
        const int bb = tid >> 4, qq = tid & 15;
        double acc64 = 0.0;
        for (int bx = 0; bx < 16; ++bx) {
            float acc32 = 0.f;
#pragma unroll
            for (int ww = 0; ww < 8; ++ww)
                acc32 += g_wsum[bb][bx * 8 + ww][qq];
            acc64 += (double)acc32;
        }
        sums[bb][qq] = acc64;
    }
    __syncthreads();
    if (tid < BB) kabsch_sums(sums[tid], Rsh[tid]);
    __syncthreads();

    if (tid < BB * 12) {
        const int bb = tid / 12, qq = tid % 12;
        const int i = qq / 4, jj = qq % 4;
        float val = (jj < 3) ? Rsh[bb][3 * i + jj] : Rsh[bb][9 + i];
        out[bb * 12 + i * 4 + jj] = val;
    }

    if (tid == 0) {
        g_gen = 0u; g_fincnt = 0u;
        g_momcntB[0] = 0u; g_momcntB[1] = 0u; g_momcntB[2] = 0u; g_momcntB[3] = 0u;
    }
}

// ---------------------------------------------------------------------------
extern "C" void kernel_launch(void* const* d_in, const int* in_sizes, int n_in,
                              void* d_out, int out_size) {
    const float* source = (const float*)d_in[0];
    const float* target = (const float*)d_in[1];
    float*       out    = (float*)d_out;

    const int smem_bytes = (NPAIRS * 8 + NQG * SRCB + SRCB * 3 + SRCB * 3 + 12) * 4
                         + 64;

    cudaFuncSetAttribute(icp_kernel,
                         cudaFuncAttributeMaxDynamicSharedMemorySize, smem_bytes);

    icp_kernel<<<NBLK, TPB, smem_bytes>>>(source, target, out);
}

// round 11
// speedup vs baseline: 1.2709x; 1.0059x over previous
#include <cuda_runtime.h>
#include <math.h>

// Problem constants
#define BB        4
#define NPTS      4096
#define MPTS      4096
#define TPB       512
#define SRCB      128               // sources per block
#define PARTS     16                // target parts (one per warp)
#define BLK_PER_B 32                // blocks per batch
#define NBLK      (BB * BLK_PER_B)  // 128 blocks total, 1 per SM
#define NPAIRS    (MPTS / 2)        // 2048 target pairs per batch
#define PPP       (NPAIRS / PARTS)  // 128 pairs per part
#define GRPS      4                 // groups per part
#define GP        (PPP / GRPS)      // 32 pairs per group
#define NQG       (PARTS * GRPS)    // 64 cells; cell t covers pairs [32t,32t+32)
#define ICP_STEPS 16
#define ICP_TOL   1e-6

// ---------------------------------------------------------------------------
// Device-global state. g_cnt is monotonic within a launch, reset by the final
// block -> replay-clean for CUDA graphs. g_wsum double-buffered by step parity
// so a step's writes never race the previous step's readers.
// ---------------------------------------------------------------------------
__device__ float    g_wsum[2][BB][128][16];
__device__ unsigned g_cnt;

// ---------------------------------------------------------------------------
__device__ __forceinline__ void xform(const float* Mtx,
                                      float px, float py, float pz,
                                      float& qx, float& qy, float& qz) {
    qx = fmaf(Mtx[0], px, fmaf(Mtx[1], py, fmaf(Mtx[2], pz, Mtx[9])));
    qy = fmaf(Mtx[3], px, fmaf(Mtx[4], py, fmaf(Mtx[5], pz, Mtx[10])));
    qz = fmaf(Mtx[6], px, fmaf(Mtx[7], py, fmaf(Mtx[8], pz, Mtx[11])));
}

// packed f32x2 helpers (per-half rounding identical to scalar FFMA)
__device__ __forceinline__ unsigned long long pk2(float v) {
    unsigned long long r;
    asm("mov.b64 %0, {%1, %1};" : "=l"(r) : "f"(v));
    return r;
}
__device__ __forceinline__ unsigned long long fma2(unsigned long long a,
                                                   unsigned long long b,
                                                   unsigned long long c) {
    unsigned long long d;
    asm("fma.rn.f32x2 %0, %1, %2, %3;" : "=l"(d) : "l"(a), "l"(b), "l"(c));
    return d;
}
__device__ __forceinline__ void upk2(unsigned long long v, float& lo, float& hi) {
    asm("mov.b64 {%0, %1}, %2;" : "=f"(lo), "=f"(hi) : "l"(v));
}

// ---------------------------------------------------------------------------
// Kabsch from accumulated sums (identical arithmetic to R2-R10).
// ---------------------------------------------------------------------------
__device__ void kabsch_sums(const double* S, float* Rt) {
    const double invN = 1.0 / (double)NPTS;
    double cs[3] = { S[0] * invN, S[1] * invN, S[2] * invN };
    double ct[3] = { S[3] * invN, S[4] * invN, S[5] * invN };

    float H[3][3];
    for (int i = 0; i < 3; ++i)
        for (int j = 0; j < 3; ++j)
            H[i][j] = (float)(S[6 + 3 * i + j] - (double)NPTS * cs[i] * ct[j]);

    float A[3][3];
    for (int i = 0; i < 3; ++i)
        for (int j = 0; j < 3; ++j)
            A[i][j] = H[0][i] * H[0][j] + H[1][i] * H[1][j] + H[2][i] * H[2][j];

    float V[3][3] = { {1,0,0},{0,1,0},{0,0,1} };
    const float diagmag = fabsf(A[0][0]) + fabsf(A[1][1]) + fabsf(A[2][2]);
    const float offeps  = diagmag * 1e-9f;
    for (int sweep = 0; sweep < 8; ++sweep) {
        const float off = fabsf(A[0][1]) + fabsf(A[0][2]) + fabsf(A[1][2]);
        if (off <= offeps) break;
        for (int pq = 0; pq < 3; ++pq) {
            const int p = (pq == 2) ? 1 : 0;
            const int q = (pq == 0) ? 1 : 2;
            const float apq = A[p][q];
            if (fabsf(apq) <= 0.0f) continue;
            const float theta = (A[q][q] - A[p][p]) / (2.0f * apq);
            const float tt = ((theta >= 0.0f) ? 1.0f : -1.0f) /
                             (fabsf(theta) + sqrtf(theta * theta + 1.0f));
            const float c = rsqrtf(tt * tt + 1.0f);
            const float s = tt * c;
            for (int k = 0; k < 3; ++k) { float a1 = A[p][k], a2 = A[q][k];
                A[p][k] = c * a1 - s * a2; A[q][k] = s * a1 + c * a2; }
            for (int k = 0; k < 3; ++k) { float a1 = A[k][p], a2 = A[k][q];
                A[k][p] = c * a1 - s * a2; A[k][q] = s * a1 + c * a2; }
            for (int k = 0; k < 3; ++k) { float v1 = V[k][p], v2 = V[k][q];
                V[k][p] = c * v1 - s * v2; V[k][q] = s * v1 + c * v2; }
        }
    }

    int id[3] = { 0, 1, 2 };
    float w[3] = { A[0][0], A[1][1], A[2][2] };
    if (w[id[0]] < w[id[1]]) { int t0 = id[0]; id[0] = id[1]; id[1] = t0; }
    if (w[id[0]] < w[id[2]]) { int t0 = id[0]; id[0] = id[2]; id[2] = t0; }
    if (w[id[1]] < w[id[2]]) { int t0 = id[1]; id[1] = id[2]; id[2] = t0; }

    float v1[3], v2[3], v3[3];
    for (int k = 0; k < 3; ++k) { v1[k] = V[k][id[0]]; v2[k] = V[k][id[1]]; v3[k] = V[k][id[2]]; }

    float u1[3], u2[3], u3[3];
    for (int i = 0; i < 3; ++i) u1[i] = H[i][0] * v1[0] + H[i][1] * v1[1] + H[i][2] * v1[2];
    {
        float n1 = u1[0]*u1[0] + u1[1]*u1[1] + u1[2]*u1[2];
        float r = (n1 > 0.0f) ? rsqrtf(n1) : 0.0f;
        u1[0] *= r; u1[1] *= r; u1[2] *= r;
    }
    for (int i = 0; i < 3; ++i) u2[i] = H[i][0] * v2[0] + H[i][1] * v2[1] + H[i][2] * v2[2];
    {
        float pr = u1[0]*u2[0] + u1[1]*u2[1] + u1[2]*u2[2];
        u2[0] -= pr * u1[0]; u2[1] -= pr * u1[1]; u2[2] -= pr * u1[2];
        float n2 = u2[0]*u2[0] + u2[1]*u2[1] + u2[2]*u2[2];
        float r = (n2 > 0.0f) ? rsqrtf(n2) : 0.0f;
        u2[0] *= r; u2[1] *= r; u2[2] *= r;
    }
    u3[0] = u1[1]*u2[2] - u1[2]*u2[1];
    u3[1] = u1[2]*u2[0] - u1[0]*u2[2];
    u3[2] = u1[0]*u2[1] - u1[1]*u2[0];

    const float d =
        v1[0] * (v2[1]*v3[2] - v2[2]*v3[1]) -
        v1[1] * (v2[0]*v3[2] - v2[2]*v3[0]) +
        v1[2] * (v2[0]*v3[1] - v2[1]*v3[0]);

    float R[9];
    for (int i = 0; i < 3; ++i)
        for (int j = 0; j < 3; ++j)
            R[3 * i + j] = v1[i]*u1[j] + v2[i]*u2[j] + d * v3[i]*u3[j];
    for (int k = 0; k < 9; ++k) Rt[k] = R[k];
    for (int i = 0; i < 3; ++i)
        Rt[9 + i] = (float)ct[i] - (R[3*i]*(float)cs[0] + R[3*i+1]*(float)cs[1]
                                    + R[3*i+2]*(float)cs[2]);
}

// ---------------------------------------------------------------------------
// Warp shfl reduction identical to the original block_reduce16 intra-warp
// stage; lane0 writes its warp row to g_wsum[buf]. Caller: threads 0..127.
// ---------------------------------------------------------------------------
__device__ __forceinline__ void warp_reduce16_store(const float v[16],
                                                    int buf, int b, int row) {
    const int lane = threadIdx.x & 31;
#pragma unroll
    for (int q = 0; q < 16; ++q) {
        float r = v[q];
#pragma unroll
        for (int o = 16; o > 0; o >>= 1) r += __shfl_down_sync(0xffffffffu, r, o);
        if (lane == 0) g_wsum[buf][b][row][q] = r;
    }
}

// ---------------------------------------------------------------------------
// Local (per-block, redundant, deterministic) fin: read g_wsum[buf], reduce
// with the EXACT summation order of earlier rounds, kabsch on threads 0..3,
// combine done flag, freeze-to-identity when done. All blocks produce
// bit-identical Rsh/errlastS/doneS.
// ---------------------------------------------------------------------------
__device__ __forceinline__ void local_fin(int buf, int k_is0,
                                          float* part1,          // [1024] smem
                                          double (*sums)[16],    // [4][16] smem
                                          float (*Rsh)[12],      // [4][12] smem
                                          double* errlastS,      // [4] smem
                                          int* convfS,           // [4] smem
                                          int* doneS) {          // [1] smem
    const int tid = threadIdx.x;

    // parallel partial sums: cell c = ((bb*16)+qq)*16+bx ; f32 over w (order!)
    for (int c = tid; c < BB * 16 * 16; c += TPB) {
        const int bb = c >> 8, rem = c & 255, qq = rem >> 4, bx = rem & 15;
        float a = 0.f;
#pragma unroll
        for (int w = 0; w < 8; ++w)
            a += g_wsum[buf][bb][bx * 8 + w][qq];
        part1[c] = a;
    }
    __syncthreads();

    if (tid < BB * 16) {
        const int bb = tid >> 4, qq = tid & 15;
        double acc = 0.0;
        for (int bx = 0; bx < 16; ++bx)
            acc += (double)part1[(bb * 16 + qq) * 16 + bx];
        sums[bb][qq] = acc;
    }
    __syncthreads();

    double errnew = 0.0;
    if (tid < BB) {
        errnew = sums[tid][15] / (double)NPTS;
        const double errlast = k_is0 ? 0.0 : errlastS[tid];
        convfS[tid] = (fabs(errnew - errlast) < ICP_TOL) ? 1 : 0;
        kabsch_sums(sums[tid], Rsh[tid]);
    }
    __syncthreads();
    if (tid == 0) {
        const int all  = convfS[0] & convfS[1] & convfS[2] & convfS[3];
        const int prev = k_is0 ? 0 : *doneS;
        *doneS = prev | all;
    }
    __syncthreads();
    if (tid < BB) {
        if (!(*doneS)) {
            errlastS[tid] = errnew;
        } else {
            for (int qq = 0; qq < 12; ++qq)
                Rsh[tid][qq] = (qq == 0 || qq == 4 || qq == 8) ? 1.f : 0.f;
        }
    }
    __syncthreads();
}

// ---------------------------------------------------------------------------
// Persistent fused ICP kernel: 128 blocks x 512 threads (1 block/SM).
// Warp w = target part (16 x 128 pairs); each lane handles 4 sources.
// Phase A: min-VALUE-only (FMNMX). Phase B: exact index recovery by rescan.
// Step transform computed redundantly by every block (no fin bottleneck).
// ---------------------------------------------------------------------------
extern __shared__ __align__(16) float smem_dyn[];

__global__ void __launch_bounds__(TPB, 1)
icp_kernel(const float* __restrict__ src, const float* __restrict__ tgt,
           float* __restrict__ out) {
    // dynamic smem layout
    float* tgP   = smem_dyn;                       // 2048 pairs * 8 f = 64KB
    float* gmins = tgP + NPAIRS * 8;               // 64 * 128 f = 32KB
    float* srcP  = gmins + NQG * SRCB;             // 128*3
    float* mw    = srcP + SRCB * 3;                // 128*3

    __shared__ float  part1[BB * 16 * 16];         // 4KB fin partials
    __shared__ double sums[BB][16];
    __shared__ float  Rsh[BB][12];
    __shared__ double errlastS[BB];
    __shared__ int    convfS[BB];
    __shared__ int    doneS;
    __shared__ int    s_isfin;

    const int tid  = threadIdx.x;
    const int w    = tid >> 5;                 // warp 0..15 == target part
    const int lane = tid & 31;
    const int b    = blockIdx.x >> 5;          // batch
    const int blk2 = blockIdx.x & 31;          // 128-source slice

    // this lane's four sources
    const int s0 = lane, s1 = lane + 32, s2 = lane + 64, s3 = lane + 96;

    // ---- stage full target set; pair p: [x0 x1 y0 y1 z0 z1 w0 w1]
    {
        const float* T = tgt + (size_t)b * MPTS * 3;
        for (int k = tid; k < MPTS; k += TPB) {
            float x = T[3 * k], y = T[3 * k + 1], z = T[3 * k + 2];
            float ww = fmaf(x, x, fmaf(y, y, z * z));
            int p = k >> 1, h = k & 1;
            tgP[p * 8 + 0 + h] = x;
            tgP[p * 8 + 2 + h] = y;
            tgP[p * 8 + 4 + h] = z;
            tgP[p * 8 + 6 + h] = ww;
        }
    }
    if (tid < SRCB * 3) {
        srcP[tid] = src[(size_t)(b * NPTS + blk2 * SRCB) * 3 + tid];
    }
    __syncthreads();

    const ulonglong2* tg2 = (const ulonglong2*)tgP;   // pair p = tg2[2p], tg2[2p+1]

    for (int k = 0; k < ICP_STEPS; ++k) {
        // ---- compute step transform locally (all blocks, bit-identical)
        if (k > 0) {
            if (tid == 0) {
                while (*(volatile unsigned*)&g_cnt < (unsigned)(NBLK * k))
                    __nanosleep(32);
                __threadfence();
            }
            __syncthreads();
            local_fin((k - 1) & 1, (k == 1), part1, sums, Rsh, errlastS,
                      convfS, &doneS);
        }

        // ---- transform this lane's four source points (identity at k==0)
        float wx[4], wy[4], wz[4];
        {
            const int ss[4] = { s0, s1, s2, s3 };
#pragma unroll
            for (int t = 0; t < 4; ++t) {
                const float px = srcP[3 * ss[t]], py = srcP[3 * ss[t] + 1],
                            pz = srcP[3 * ss[t] + 2];
                if (k == 0) {
                    const float I[12] = {1.f,0.f,0.f, 0.f,1.f,0.f, 0.f,0.f,1.f,
                                         0.f,0.f,0.f};
                    xform(I, px, py, pz, wx[t], wy[t], wz[t]);
                } else {
                    xform(Rsh[b], px, py, pz, wx[t], wy[t], wz[t]);
                }
            }
        }

        // ================= Phase A: min-value-only scan, 4 sources ==========
        {
            unsigned long long ax[4], ay[4], az[4];
#pragma unroll
            for (int t = 0; t < 4; ++t) {
                ax[t] = pk2(-2.f * wx[t]);
                ay[t] = pk2(-2.f * wy[t]);
                az[t] = pk2(-2.f * wz[t]);
            }
            const int pbase = w * PPP;

#pragma unroll
            for (int grp = 0; grp < GRPS; ++grp) {
                const int gp = pbase + grp * GP;
                float gmE[4] = { 3.4e38f, 3.4e38f, 3.4e38f, 3.4e38f };
                float gmO[4] = { 3.4e38f, 3.4e38f, 3.4e38f, 3.4e38f };
#pragma unroll 4
                for (int i = 0; i < GP; ++i) {
                    const ulonglong2 A  = tg2[2 * (gp + i)];
                    const ulonglong2 Bv = tg2[2 * (gp + i) + 1];
#pragma unroll
                    for (int t = 0; t < 4; ++t) {
                        unsigned long long s01 =
                            fma2(ax[t], A.x, fma2(ay[t], A.y,
                                 fma2(az[t], Bv.x, Bv.y)));
                        float e, o;
                        upk2(s01, e, o);
                        gmE[t] = fminf(gmE[t], e);
                        gmO[t] = fminf(gmO[t], o);
                    }
                }
                const int cell = (w * GRPS + grp) * SRCB;
                gmins[cell + s0] = fminf(gmE[0], gmO[0]);
                gmins[cell + s1] = fminf(gmE[1], gmO[1]);
                gmins[cell + s2] = fminf(gmE[2], gmO[2]);
                gmins[cell + s3] = fminf(gmE[3], gmO[3]);
            }
        }
        if (w == 0) {   // one copy of the transformed points per source
            mw[3 * s0] = wx[0]; mw[3 * s0 + 1] = wy[0]; mw[3 * s0 + 2] = wz[0];
            mw[3 * s1] = wx[1]; mw[3 * s1 + 1] = wy[1]; mw[3 * s1 + 2] = wz[1];
            mw[3 * s2] = wx[2]; mw[3 * s2 + 1] = wy[2]; mw[3 * s2 + 2] = wz[2];
            mw[3 * s3] = wx[3]; mw[3 * s3 + 1] = wy[3]; mw[3 * s3 + 2] = wz[3];
        }
        __syncthreads();

        // ============ Phase B + moments (threads 0..127, src = tid) ========
        if (tid < SRCB) {
            float m = gmins[tid];
#pragma unroll 8
            for (int t = 1; t < NQG; ++t) m = fminf(m, gmins[t * SRCB + tid]);

            int qg = 0;
#pragma unroll 8
            for (int t = NQG - 1; t >= 0; --t)
                if (gmins[t * SRCB + tid] == m) qg = t;

            const float mx = mw[3 * tid], my = mw[3 * tid + 1], mz = mw[3 * tid + 2];
            const unsigned long long ax2 = pk2(-2.f * mx);
            const unsigned long long ay2 = pk2(-2.f * my);
            const unsigned long long az2 = pk2(-2.f * mz);
            const int pstart = qg * GP;

            int jb = 0xFFFF;
#pragma unroll 4
            for (int i = 0; i < GP; ++i) {
                const ulonglong2 A  = tg2[2 * (pstart + i)];
                const ulonglong2 Bv = tg2[2 * (pstart + i) + 1];
                unsigned long long s01 =
                    fma2(ax2, A.x, fma2(ay2, A.y, fma2(az2, Bv.x, Bv.y)));
                float e, o;
                upk2(s01, e, o);
                if (e == m) jb = min(jb, 2 * (pstart + i));
                if (o == m) jb = min(jb, 2 * (pstart + i) + 1);
            }
            const unsigned j = (unsigned)jb;
            const float    s = m;

            const float a2v = fmaf(mx, mx, fmaf(my, my, mz * mz));
            const float d2  = fmaxf(s + a2v, 0.f);
            const float ec  = sqrtf(d2);

            const unsigned p = j >> 1, h = j & 1;
            const float tx = tgP[p * 8 + 0 + h];
            const float ty = tgP[p * 8 + 2 + h];
            const float tz = tgP[p * 8 + 4 + h];

            const float v[16] = { mx, my, mz, tx, ty, tz,
                                  mx * tx, mx * ty, mx * tz,
                                  my * tx, my * ty, my * tz,
                                  mz * tx, mz * ty, mz * tz, ec };
            warp_reduce16_store(v, k & 1, b, blk2 * 4 + (tid >> 5));

            srcP[3 * tid] = mx; srcP[3 * tid + 1] = my; srcP[3 * tid + 2] = mz;
        }
        __threadfence();
        __syncthreads();
        if (tid == 0) atomicAdd(&g_cnt, 1u);   // arrival; spin at next fin
    }

    // ======================= FINAL kabsch(source, temporal) ==================
    if (tid == 0) {
        while (*(volatile unsigned*)&g_cnt < (unsigned)(NBLK * ICP_STEPS))
            __nanosleep(32);
        __threadfence();
    }
    __syncthreads();
    local_fin((ICP_STEPS - 1) & 1, 0, part1, sums, Rsh, errlastS, convfS, &doneS);

    if (tid < SRCB) {
        const float px = srcP[3 * tid], py = srcP[3 * tid + 1], pz = srcP[3 * tid + 2];
        float wxf, wyf, wzf;
        xform(Rsh[b], px, py, pz, wxf, wyf, wzf);

        const float sx = src[3 * (b * NPTS + blk2 * SRCB + tid)];
        const float sy = src[3 * (b * NPTS + blk2 * SRCB + tid) + 1];
        const float sz = src[3 * (b * NPTS + blk2 * SRCB + tid) + 2];

        const float v[16] = { sx, sy, sz, wxf, wyf, wzf,
                              sx * wxf, sx * wyf, sx * wzf,
                              sy * wxf, sy * wyf, sy * wzf,
                              sz * wxf, sz * wyf, sz * wzf, 0.f };
        warp_reduce16_store(v, 0, b, blk2 * 4 + (tid >> 5));   // buf 0 (16&1)
    }
    __threadfence();
    __syncthreads();
    if (tid == 0) {
        unsigned old = atomicAdd(&g_cnt, 1u);
        s_isfin = (old == (unsigned)(NBLK * (ICP_STEPS + 1) - 1)) ? 1 : 0;
    }
    __syncthreads();
    if (!s_isfin) return;

    // ---- last block: final sums + kabsch, output, counter reset
    if (tid == 0) __threadfence();
    __syncthreads();
    for (int c = tid; c < BB * 16 * 16; c += TPB) {
        const int bb = c >> 8, rem = c & 255, qq = rem >> 4, bx = rem & 15;
        float a = 0.f;
#pragma unroll
        for (int ww = 0; ww < 8; ++ww)
            a += g_wsum[0][bb][bx * 8 + ww][qq];
        part1[c] = a;
    }
    __syncthreads();
    if (tid < BB * 16) {
        const int bb = tid >> 4, qq = tid & 15;
        double acc = 0.0;
        for (int bx = 0; bx < 16; ++bx)
            acc += (double)part1[(bb * 16 + qq) * 16 + bx];
        sums[bb][qq] = acc;
    }
    __syncthreads();
    if (tid < BB) kabsch_sums(sums[tid], Rsh[tid]);
    __syncthreads();

    if (tid < BB * 12) {
        const int bb = tid / 12, qq = tid % 12;
        const int i = qq / 4, jj = qq % 4;
        float val = (jj < 3) ? Rsh[bb][3 * i + jj] : Rsh[bb][9 + i];
        out[bb * 12 + i * 4 + jj] = val;
    }

    if (tid == 0) g_cnt = 0u;
}

// ---------------------------------------------------------------------------
extern "C" void kernel_launch(void* const* d_in, const int* in_sizes, int n_in,
                              void* d_out, int out_size) {
    const float* source = (const float*)d_in[0];
    const float* target = (const float*)d_in[1];
    float*       out    = (float*)d_out;

    const int smem_bytes = (NPAIRS * 8 + NQG * SRCB + SRCB * 3 + SRCB * 3) * 4
                         + 64;

    cudaFuncSetAttribute(icp_kernel,
                         cudaFuncAttributeMaxDynamicSharedMemorySize, smem_bytes);

    icp_kernel<<<NBLK, TPB, smem_bytes>>>(source, target, out);
}